// round 13
// baseline (speedup 1.0000x reference)
#include <cuda_runtime.h>
#include <cuda_fp16.h>
#include <cstdint>

#define BB   16
#define LL   512
#define CC   256
#define MEL  4096

typedef unsigned long long ull;

// ---------------------------------------------------------------------------
// Scratch + flags (__device__ globals; zero-initialized at load, and every
// flag is reset by its unique consumer so graph replays stay deterministic)
// ---------------------------------------------------------------------------
__device__ uint32_t g_h1pk[BB * LL * 128];        // h1 packed half2 [b][l][kpair]
__device__ int      g_idx[BB * MEL];              // per-frame token index
__device__ uint32_t g_wpk[2 * 3 * 128 * 256];     // weights packed half2
__device__ int      g_fprep[128];                 // prep-done, one per conv1 CTA
__device__ int      g_fh1[BB][8][3];              // h1-tile flags per conv2 CTA
__device__ unsigned g_prep_ct;                    // prep completion counter

// ---------------------------------------------------------------------------
__device__ __forceinline__ uint32_t pack_h2(float a, float b) {
    __half2 h = __floats2half2_rn(a, b);
    return *reinterpret_cast<uint32_t*>(&h);
}
__device__ __forceinline__ void mma_f16(float* d, const uint32_t* a, const uint32_t* b) {
    asm volatile(
        "mma.sync.aligned.m16n8k16.row.col.f32.f16.f16.f32 "
        "{%0,%1,%2,%3}, {%4,%5,%6,%7}, {%8,%9}, {%0,%1,%2,%3};"
        : "+f"(d[0]), "+f"(d[1]), "+f"(d[2]), "+f"(d[3])
        : "r"(a[0]), "r"(a[1]), "r"(a[2]), "r"(a[3]), "r"(b[0]), "r"(b[1]));
}
__device__ __forceinline__ uint32_t smem_u32(const void* p) {
    uint32_t a;
    asm("{ .reg .u64 t; cvta.to.shared.u64 t, %1; cvt.u32.u64 %0, t; }"
        : "=r"(a) : "l"(p));
    return a;
}
__device__ __forceinline__ void spin_flag(int* p) {
    while (atomicAdd(p, 0) == 0) { __nanosleep(60); }
}
#define CP_ASYNC16(dst, src) \
    asm volatile("cp.async.ca.shared.global [%0], [%1], 16;" :: "r"(dst), "l"(src))
#define CP_COMMIT() asm volatile("cp.async.commit_group;" ::: "memory")
#define CP_WAIT2()  asm volatile("cp.async.wait_group 2;" ::: "memory")
#define CP_WAIT1()  asm volatile("cp.async.wait_group 1;" ::: "memory")
#define CP_WAIT0()  asm volatile("cp.async.wait_group 0;" ::: "memory")

// smem geometry (uint32 units).
#define A_STR 132
#define B_STR 264
#define A_U32 (66 * A_STR)               // 8712
#define B32_U32 (32 * B_STR)             // 8448 (one 32-kpair chunk)
#define IDX_OFF (A_U32 + 4 * B32_U32)    // 42504
#define SMEM_BYTES ((IDX_OFF + 256) * 4) // 171040

#define P_CTAS  40
#define C1_BASE 40
#define C2_BASE 168
#define GRID    296

// ---------------------------------------------------------------------------
// Conv body: conv1d(K=3,SAME)+bias+ReLU+LN [+linear head if FINAL], fp16 MMA.
// CTA = [64 l x 256 f], 256 threads / 8 warps, warp tile 64x32.
// ---------------------------------------------------------------------------
template <bool FINAL>
__device__ __forceinline__ void conv_body(
    int b, int t,
    const float* __restrict__ xin,
    const float* __restrict__ bias,
    const float* __restrict__ gamma,
    const float* __restrict__ beta,
    const float* __restrict__ linw,
    const float* __restrict__ linb,
    float* __restrict__ predout,
    float* __restrict__ regout,
    uint32_t* smu)
{
    uint32_t* sA2 = smu;
    int* sIdx = (int*)(smu + IDX_OFF);
    const uint32_t sa_u32 = smem_u32(sA2);
    const uint32_t sb_base = sa_u32 + A_U32 * 4;
    const uint32_t sidx_u32 = smem_u32(sIdx);

    const int tid  = threadIdx.x;
    const int warp = tid >> 5, lane = tid & 31;
    const int g = lane >> 2, q = lane & 3;
    const int n0 = warp * 32;
    const int l0 = t * 64;
    const int CONV = FINAL ? 1 : 0;
    const int fbase = t * 512 + (FINAL ? 256 : 0);

    auto stageB = [&](int ck) {
        const int buf = ck & 3;
        const uint32_t* src = g_wpk + ((size_t)(CONV * 3 + (ck >> 2)) * 128 + (ck & 3) * 32) * 256;
        const uint32_t bdst = sb_base + (uint32_t)buf * B32_U32 * 4;
#pragma unroll
        for (int i = 0; i < 8; i++) {
            int idx = tid + i * 256;
            int c = idx >> 6, n4 = idx & 63;
            CP_ASYNC16(bdst + (uint32_t)(c * B_STR + n4 * 4) * 4,
                       src + (size_t)c * 256 + n4 * 4);
        }
        CP_COMMIT();
    };

    if (!FINAL) {
        // ---- A inline pack from fp32 x (overlaps prep on other SMs) ----
        const float* inb = xin + (size_t)b * LL * CC;
#pragma unroll 4
        for (int i = 0; i < 17; i++) {
            int idx = tid + i * 256;
            if (idx < 66 * 64) {
                int c4 = idx & 63, row = idx >> 6;
                int grow = l0 + row - 1;
                float4 v = make_float4(0.f, 0.f, 0.f, 0.f);
                if (grow >= 0 && grow < LL)
                    v = *(const float4*)(inb + (size_t)grow * CC + c4 * 4);
                uint32_t h01 = pack_h2(v.x, v.y);
                uint32_t h23 = pack_h2(v.z, v.w);
                *(ull*)(sA2 + row * A_STR + c4 * 2) = ((ull)h23 << 32) | h01;
            }
        }
        // ---- wait for prep (weights + idx) ----
        if (tid == 0) {
            int c1id = b * 8 + t;
            spin_flag(&g_fprep[c1id]);
            g_fprep[c1id] = 0;
            __threadfence();
        }
        __syncthreads();
        stageB(0);                                  // g0
        if (tid < 64)
            CP_ASYNC16(sidx_u32 + tid * 16, g_idx + b * MEL + fbase + tid * 4);
        CP_COMMIT();                                // g1
        stageB(1);                                  // g2
        stageB(2);                                  // g3
    } else {
        // ---- wait for the (up to) 3 producer h1 tiles ----
        if (tid < 3) {
            bool need = (tid == 1) || (tid == 0 && t > 0) || (tid == 2 && t < 7);
            if (need) {
                spin_flag(&g_fh1[b][t][tid]);
                g_fh1[b][t][tid] = 0;
                __threadfence();
            }
        }
        __syncthreads();
        stageB(0);                                  // g0
        {
            const uint32_t* apk = g_h1pk + (size_t)b * LL * 128;
#pragma unroll
            for (int i = 0; i < 9; i++) {
                int idx = tid + i * 256;            // need 66*32 = 2112 segs
                if (idx < 66 * 32) {
                    int row = idx >> 5, seg = idx & 31;
                    int grow = l0 + row - 1;
                    if (grow >= 0 && grow < LL)
                        CP_ASYNC16(sa_u32 + (uint32_t)(row * A_STR + seg * 4) * 4,
                                   apk + (size_t)grow * 128 + seg * 4);
                    else
                        *(float4*)(sA2 + row * A_STR + seg * 4) =
                            make_float4(0.f, 0.f, 0.f, 0.f);
                }
            }
            if (tid < 64)
                CP_ASYNC16(sidx_u32 + tid * 16, g_idx + b * MEL + fbase + tid * 4);
            CP_COMMIT();                            // g1
        }
        stageB(1);                                  // g2
        stageB(2);                                  // g3
    }

    float acc[4][4][4];
#pragma unroll
    for (int mt = 0; mt < 4; mt++)
#pragma unroll
        for (int nt = 0; nt < 4; nt++)
#pragma unroll
            for (int r = 0; r < 4; r++) acc[mt][nt][r] = 0.f;

    for (int it = 0; it < 12; it++) {
        const int ktap = it >> 2, koff = (it & 3) * 32;
        if (it <= 9) CP_WAIT2();
        else if (it == 10) CP_WAIT1();
        else CP_WAIT0();
        __syncthreads();
        if (it + 3 < 12) stageB(it + 3);

        // ---- regulate: issue gathers now; latency hides under MMA ----
        int ix[6];
        float4 vv[6];
#pragma unroll
        for (int u = 0; u < 6; u++) {
            int s = it * 6 + u;
            ix[u] = (s < 64) ? sIdx[(tid + s * 256) >> 6] : -1;
        }
#pragma unroll
        for (int u = 0; u < 6; u++) {
            vv[u] = make_float4(0.f, 0.f, 0.f, 0.f);
            if (ix[u] >= 0) {
                int s = it * 6 + u;
                int c4 = (tid + s * 256) & 63;
                vv[u] = *(const float4*)(xin + ((size_t)b * LL + ix[u]) * CC + c4 * 4);
            }
        }

        const uint32_t* ab = sA2 + (ktap + g) * A_STR + koff + q;
        const uint32_t* bb = (uint32_t*)(smu + A_U32 + (it & 3) * B32_U32) + n0 + g;
#pragma unroll
        for (int ks = 0; ks < 4; ks++) {
            uint32_t af[4][4], bf[4][2];
#pragma unroll
            for (int mt = 0; mt < 4; mt++) {
                const uint32_t* ap = ab + mt * (16 * A_STR) + ks * 8;
                af[mt][0] = ap[0];
                af[mt][1] = ap[8 * A_STR];
                af[mt][2] = ap[4];
                af[mt][3] = ap[8 * A_STR + 4];
            }
#pragma unroll
            for (int nt = 0; nt < 4; nt++) {
                bf[nt][0] = bb[(ks * 8 + q) * B_STR + nt * 8];
                bf[nt][1] = bb[(ks * 8 + q + 4) * B_STR + nt * 8];
            }
#pragma unroll
            for (int mt = 0; mt < 4; mt++)
#pragma unroll
                for (int nt = 0; nt < 4; nt++)
                    mma_f16(acc[mt][nt], af[mt], bf[nt]);
        }

#pragma unroll
        for (int u = 0; u < 6; u++) {
            int s = it * 6 + u;
            if (s < 64) {
                int j = tid + s * 256;
                int fr = j >> 6, c4 = j & 63;
                *(float4*)(regout + ((size_t)b * MEL + fbase + fr) * CC + c4 * 4) = vv[u];
            }
        }
    }
    __syncthreads();

    // ---- epilogue: bias + ReLU + LN (fused), optional linear head ----
    float bi[8], ga[8], be[8], lw[8];
#pragma unroll
    for (int nt = 0; nt < 4; nt++)
#pragma unroll
        for (int j = 0; j < 2; j++) {
            int c = n0 + nt * 8 + 2 * q + j;
            bi[nt * 2 + j] = __ldg(bias + c);
            ga[nt * 2 + j] = __ldg(gamma + c);
            be[nt * 2 + j] = __ldg(beta + c);
            if (FINAL) lw[nt * 2 + j] = __ldg(linw + c);
        }

    float v[4][2][8];
    float2* red   = (float2*)sA2;                  // [64 rows][8 warps]
    float2* stats = red + 512;                     // [64]
    float*  dred  = (float*)sA2 + 2048;            // [64 rows][8 warps]

#pragma unroll
    for (int mt = 0; mt < 4; mt++)
#pragma unroll
        for (int h = 0; h < 2; h++) {
            float s = 0.f, s2 = 0.f;
#pragma unroll
            for (int nt = 0; nt < 4; nt++)
#pragma unroll
                for (int j = 0; j < 2; j++) {
                    float x = acc[mt][nt][h * 2 + j] + bi[nt * 2 + j];
                    x = fmaxf(x, 0.f);
                    v[mt][h][nt * 2 + j] = x;
                    s += x; s2 += x * x;
                }
            s  += __shfl_xor_sync(0xffffffffu, s, 1);
            s2 += __shfl_xor_sync(0xffffffffu, s2, 1);
            s  += __shfl_xor_sync(0xffffffffu, s, 2);
            s2 += __shfl_xor_sync(0xffffffffu, s2, 2);
            if (q == 0)
                red[(mt * 16 + g + 8 * h) * 8 + warp] = make_float2(s, s2);
        }
    __syncthreads();
    if (tid < 64) {
        float s = 0.f, s2 = 0.f;
#pragma unroll
        for (int wv = 0; wv < 8; wv++) {
            float2 p = red[tid * 8 + wv];
            s += p.x; s2 += p.y;
        }
        float mu = s * (1.f / 256.f);
        float var = s2 * (1.f / 256.f) - mu * mu;
        stats[tid] = make_float2(mu, rsqrtf(var + 1e-5f));
    }
    __syncthreads();

    if (!FINAL) {
#pragma unroll
        for (int mt = 0; mt < 4; mt++)
#pragma unroll
            for (int h = 0; h < 2; h++) {
                int r = mt * 16 + g + 8 * h;
                float2 st = stats[r];
                uint32_t* orow = g_h1pk + ((size_t)b * LL + l0 + r) * 128 + warp * 16;
#pragma unroll
                for (int nt = 0; nt < 4; nt++) {
                    float ox = (v[mt][h][nt * 2]     - st.x) * st.y * ga[nt * 2]     + be[nt * 2];
                    float oy = (v[mt][h][nt * 2 + 1] - st.x) * st.y * ga[nt * 2 + 1] + be[nt * 2 + 1];
                    orow[nt * 4 + q] = pack_h2(ox, oy);
                }
            }
        // ---- release this h1 tile to its conv2 consumers ----
        __threadfence();
        __syncthreads();
        if (tid == 0)                 atomicExch(&g_fh1[b][t][1], 1);
        else if (tid == 1 && t > 0)   atomicExch(&g_fh1[b][t - 1][2], 1);
        else if (tid == 2 && t < 7)   atomicExch(&g_fh1[b][t + 1][0], 1);
    } else {
#pragma unroll
        for (int mt = 0; mt < 4; mt++)
#pragma unroll
            for (int h = 0; h < 2; h++) {
                int r = mt * 16 + g + 8 * h;
                float2 st = stats[r];
                float d = 0.f;
#pragma unroll
                for (int p = 0; p < 8; p++)
                    d += ((v[mt][h][p] - st.x) * st.y * ga[p] + be[p]) * lw[p];
                d += __shfl_xor_sync(0xffffffffu, d, 1);
                d += __shfl_xor_sync(0xffffffffu, d, 2);
                if (q == 0) dred[r * 8 + warp] = d;
            }
        __syncthreads();
        if (tid < 64) {
            float d = 0.f;
#pragma unroll
            for (int wv = 0; wv < 8; wv++) d += dred[tid * 8 + wv];
            predout[b * LL + l0 + tid] = d + __ldg(linb);
        }
    }
}

// ---------------------------------------------------------------------------
// Fused kernel: bids 0..23 w-pack, 24..39 cumsum/idx, 40..167 conv1, 168..295 conv2
// ---------------------------------------------------------------------------
__global__ void __launch_bounds__(256, 1)
fused_kernel(const float* __restrict__ x,
             const int*   __restrict__ dur,
             const float* __restrict__ w1,
             const float* __restrict__ w2,
             const float* __restrict__ c1b,
             const float* __restrict__ ln1g,
             const float* __restrict__ ln1b,
             const float* __restrict__ c2b,
             const float* __restrict__ ln2g,
             const float* __restrict__ ln2b,
             const float* __restrict__ linw,
             const float* __restrict__ linb,
             float* __restrict__ outp,
             float* __restrict__ pred)
{
    extern __shared__ __align__(16) uint32_t smu[];
    const int bid = blockIdx.x;
    const int tid = threadIdx.x;

    if (bid < P_CTAS) {
        if (bid < 24) {
            // ---- weight fp16 pack ----
            int base = bid * 256 + tid;
#pragma unroll
            for (int r = 0; r < 8; r++) {
                int id = base + r * 6144;          // 0..49151
                int n4 = id & 63;
                int kp = (id >> 6) & 127;
                int tt = id >> 13;                 // 0..5
                int tap = tt % 3, conv = tt / 3;
                const float* src = (conv ? w2 : w1) + (size_t)tap * 65536
                                 + (size_t)(2 * kp) * 256 + n4 * 4;
                float4 lo = *(const float4*)(src);
                float4 hi = *(const float4*)(src + 256);
                uint4 o;
                o.x = pack_h2(lo.x, hi.x);
                o.y = pack_h2(lo.y, hi.y);
                o.z = pack_h2(lo.z, hi.z);
                o.w = pack_h2(lo.w, hi.w);
                *(uint4*)(g_wpk + ((size_t)(conv * 3 + tap) * 128 + kp) * 256 + n4 * 4) = o;
            }
        } else {
            // ---- cumsum + frame->token idx (b = bid-24) ----
            int* s = (int*)smu;
            int* wsum = s + 512;
            int b = bid - 24;
            int lane = tid & 31, wid = tid >> 5;
            int d0 = dur[b * LL + 2 * tid];
            int d1 = dur[b * LL + 2 * tid + 1];
            int v = d0 + d1;
#pragma unroll
            for (int off = 1; off < 32; off <<= 1) {
                int tmp = __shfl_up_sync(0xffffffffu, v, off);
                if (lane >= off) v += tmp;
            }
            if (lane == 31) wsum[wid] = v;
            __syncthreads();
            if (wid == 0 && lane < 8) {
                int w = wsum[lane];
#pragma unroll
                for (int off = 1; off < 8; off <<= 1) {
                    int tmp = __shfl_up_sync(0xffu, w, off);
                    if (lane >= off) w += tmp;
                }
                wsum[lane] = w;
            }
            __syncthreads();
            int incl = v + (wid > 0 ? wsum[wid - 1] : 0);
            s[2 * tid]     = incl - d1;
            s[2 * tid + 1] = incl;
            __syncthreads();
            int total = s[LL - 1];
#pragma unroll
            for (int r = 0; r < 16; r++) {
                int tt = tid + r * 256;
                int lo = 0, hi = LL;
                while (lo < hi) {
                    int mid = (lo + hi) >> 1;
                    if (s[mid] <= tt) lo = mid + 1; else hi = mid;
                }
                g_idx[b * MEL + tt] = (tt < total) ? min(lo, LL - 1) : -1;
            }
        }
        // ---- prep completion: last CTA releases all conv1 CTAs ----
        __threadfence();
        __syncthreads();
        if (tid == 0) {
            unsigned c = atomicAdd(&g_prep_ct, 1u);
            if ((c % (unsigned)P_CTAS) == (unsigned)(P_CTAS - 1)) {
                for (int i = 0; i < 128; i++) atomicExch(&g_fprep[i], 1);
            }
        }
        return;
    }

    if (bid < C2_BASE) {
        int id = bid - C1_BASE;
        conv_body<false>(id >> 3, id & 7, x, c1b, ln1g, ln1b,
                         nullptr, nullptr, nullptr, outp, smu);
    } else {
        int id = bid - C2_BASE;
        conv_body<true>(id >> 3, id & 7, x, c2b, ln2g, ln2b,
                        linw, linb, pred, outp, smu);
    }
}

// ---------------------------------------------------------------------------
extern "C" void kernel_launch(void* const* d_in, const int* in_sizes, int n_in,
                              void* d_out, int out_size)
{
    const float* x    = (const float*)d_in[0];
    const int*   dur  = (const int*)d_in[1];
    const float* c1w  = (const float*)d_in[2];
    const float* c1b  = (const float*)d_in[3];
    const float* ln1g = (const float*)d_in[4];
    const float* ln1b = (const float*)d_in[5];
    const float* c2w  = (const float*)d_in[6];
    const float* c2b  = (const float*)d_in[7];
    const float* ln2g = (const float*)d_in[8];
    const float* ln2b = (const float*)d_in[9];
    const float* linw = (const float*)d_in[10];
    const float* linb = (const float*)d_in[11];

    float* out  = (float*)d_out;
    float* pred = out + (size_t)BB * MEL * CC;

    cudaFuncSetAttribute(fused_kernel,
                         cudaFuncAttributeMaxDynamicSharedMemorySize, SMEM_BYTES);

    fused_kernel<<<GRID, 256, SMEM_BYTES>>>(x, dur, c1w, c2w,
                                            c1b, ln1g, ln1b,
                                            c2b, ln2g, ln2b,
                                            linw, linb, out, pred);
}

// round 14
// speedup vs baseline: 1.0038x; 1.0038x over previous
#include <cuda_runtime.h>
#include <cuda_fp16.h>
#include <cstdint>

#define BB   16
#define LL   512
#define CC   256
#define MEL  4096

typedef unsigned long long ull;

// ---------------------------------------------------------------------------
// Scratch (__device__ globals — allocations are forbidden)
// ---------------------------------------------------------------------------
__device__ uint32_t g_h1pk[BB * LL * 128];        // h1 packed half2 [b][l][kpair]
__device__ int      g_idx[BB * MEL];              // per-frame token index
__device__ uint32_t g_wpk[2 * 3 * 128 * 256];     // weights packed half2 [conv][tap][kpair][n]

// ---------------------------------------------------------------------------
__device__ __forceinline__ uint32_t pack_h2(float a, float b) {
    __half2 h = __floats2half2_rn(a, b);
    return *reinterpret_cast<uint32_t*>(&h);
}
__device__ __forceinline__ void mma_f16(float* d, const uint32_t* a, const uint32_t* b) {
    asm volatile(
        "mma.sync.aligned.m16n8k16.row.col.f32.f16.f16.f32 "
        "{%0,%1,%2,%3}, {%4,%5,%6,%7}, {%8,%9}, {%0,%1,%2,%3};"
        : "+f"(d[0]), "+f"(d[1]), "+f"(d[2]), "+f"(d[3])
        : "r"(a[0]), "r"(a[1]), "r"(a[2]), "r"(a[3]), "r"(b[0]), "r"(b[1]));
}
__device__ __forceinline__ uint32_t smem_u32(const void* p) {
    uint32_t a;
    asm("{ .reg .u64 t; cvta.to.shared.u64 t, %1; cvt.u32.u64 %0, t; }"
        : "=r"(a) : "l"(p));
    return a;
}
#define CP_ASYNC16(dst, src) \
    asm volatile("cp.async.ca.shared.global [%0], [%1], 16;" :: "r"(dst), "l"(src))
#define CP_COMMIT() asm volatile("cp.async.commit_group;" ::: "memory")
#define CP_WAIT2()  asm volatile("cp.async.wait_group 2;" ::: "memory")
#define CP_WAIT1()  asm volatile("cp.async.wait_group 1;" ::: "memory")
#define CP_WAIT0()  asm volatile("cp.async.wait_group 0;" ::: "memory")

// smem geometry (uint32 units).
#define A_STR 132
#define B_STR 264
#define A_U32 (66 * A_STR)               // 8712
#define B32_U32 (32 * B_STR)             // 8448 (one 32-kpair chunk)
#define IDX_OFF (A_U32 + 4 * B32_U32)    // 42504
#define SMEM_BYTES ((IDX_OFF + 256) * 4) // 171040

// ---------------------------------------------------------------------------
// Prep: weight fp16 pack (blocks 0..47) + cumsum/frame-idx (blocks 48..63)
// (x-pack deleted: conv1 packs its own A tile inline)
// ---------------------------------------------------------------------------
__global__ void __launch_bounds__(512) prep_kernel(const float* __restrict__ w1,
                                                   const float* __restrict__ w2,
                                                   const int* __restrict__ dur)
{
    if (blockIdx.x < 48) {
        int idx = blockIdx.x * 512 + threadIdx.x;      // 0..24575; +24576
#pragma unroll
        for (int r = 0; r < 2; r++) {
            int id = idx + r * 24576;
            int n4 = id & 63;
            int kp = (id >> 6) & 127;
            int t  = id >> 13;                         // 0..5
            int tap = t % 3, conv = t / 3;
            const float* src = (conv ? w2 : w1) + (size_t)tap * 65536
                             + (size_t)(2 * kp) * 256 + n4 * 4;
            float4 lo = *(const float4*)(src);
            float4 hi = *(const float4*)(src + 256);
            uint4 o;
            o.x = pack_h2(lo.x, hi.x);
            o.y = pack_h2(lo.y, hi.y);
            o.z = pack_h2(lo.z, hi.z);
            o.w = pack_h2(lo.w, hi.w);
            *(uint4*)(g_wpk + ((size_t)(conv * 3 + tap) * 128 + kp) * 256 + n4 * 4) = o;
        }
        return;
    }
    // cumsum + frame->token idx, warp-shuffle scan
    __shared__ int s[LL];
    __shared__ int wsum[16];
    int b = blockIdx.x - 48, tid = threadIdx.x;
    int lane = tid & 31, wid = tid >> 5;
    int v = dur[b * LL + tid];
#pragma unroll
    for (int off = 1; off < 32; off <<= 1) {
        int t = __shfl_up_sync(0xffffffffu, v, off);
        if (lane >= off) v += t;
    }
    if (lane == 31) wsum[wid] = v;
    __syncthreads();
    if (wid == 0 && lane < 16) {
        int w = wsum[lane];
#pragma unroll
        for (int off = 1; off < 16; off <<= 1) {
            int t = __shfl_up_sync(0xffffu, w, off);
            if (lane >= off) w += t;
        }
        wsum[lane] = w;
    }
    __syncthreads();
    if (wid > 0) v += wsum[wid - 1];
    s[tid] = v;
    __syncthreads();
    int total = s[LL - 1];
#pragma unroll
    for (int r = 0; r < 8; r++) {
        int t = tid + r * 512;
        int lo = 0, hi = LL;
        while (lo < hi) {
            int mid = (lo + hi) >> 1;
            if (s[mid] <= t) lo = mid + 1; else hi = mid;
        }
        g_idx[b * MEL + t] = (t < total) ? min(lo, LL - 1) : -1;
    }
}

// ---------------------------------------------------------------------------
// Fused conv1d(K=3,SAME)+bias+ReLU+LN [+linear head if FINAL], fp16 MMA.
// CTA = [64 l x 256 f], 256 threads / 8 warps, warp tile 64x32.
// Conv1: A packed inline from fp32 x. Conv2: A via cp.async from packed h1.
// B in a 4-buffer, 32-kpair, 12-iter cp.async pipeline (ONE barrier per iter).
// Each conv streams half the regulate output; gathers issued before MMA.
// ---------------------------------------------------------------------------
template <bool FINAL>
__global__ void __launch_bounds__(256, 1)
conv_mma_kernel(const float* __restrict__ xin,
                const float* __restrict__ bias,
                const float* __restrict__ gamma,
                const float* __restrict__ beta,
                const float* __restrict__ linw,
                const float* __restrict__ linb,
                float* __restrict__ predout,
                float* __restrict__ regout)
{
    extern __shared__ __align__(16) uint32_t smu[];
    uint32_t* sA2 = smu;
    int* sIdx = (int*)(smu + IDX_OFF);
    const uint32_t sa_u32 = smem_u32(sA2);
    const uint32_t sb_base = sa_u32 + A_U32 * 4;
    const uint32_t sidx_u32 = smem_u32(sIdx);

    const int tid  = threadIdx.x;
    const int warp = tid >> 5, lane = tid & 31;
    const int g = lane >> 2, q = lane & 3;
    const int n0 = warp * 32;
    const int b  = blockIdx.y;
    const int l0 = blockIdx.x * 64;
    const int CONV = FINAL ? 1 : 0;
    const int fbase = blockIdx.x * 512 + (FINAL ? 256 : 0);

    // stage one 32-kpair chunk ck (0..11) into buffer ck&3
    auto stageB = [&](int ck) {
        const int buf = ck & 3;
        const uint32_t* src = g_wpk + ((size_t)(CONV * 3 + (ck >> 2)) * 128 + (ck & 3) * 32) * 256;
        const uint32_t bdst = sb_base + (uint32_t)buf * B32_U32 * 4;
#pragma unroll
        for (int i = 0; i < 8; i++) {
            int idx = tid + i * 256;               // 0..2047 16B segs
            int c = idx >> 6, n4 = idx & 63;
            CP_ASYNC16(bdst + (uint32_t)(c * B_STR + n4 * 4) * 4,
                       src + (size_t)c * 256 + n4 * 4);
        }
        CP_COMMIT();
    };

    if (!FINAL) {
        // ---- A inline pack from fp32 x (STS; visible at first mainloop barrier) ----
        const float* inb = xin + (size_t)b * LL * CC;
#pragma unroll 4
        for (int i = 0; i < 17; i++) {
            int idx = tid + i * 256;               // need 66*64 = 4224
            if (idx < 66 * 64) {
                int c4 = idx & 63, row = idx >> 6;
                int grow = l0 + row - 1;
                float4 v = make_float4(0.f, 0.f, 0.f, 0.f);
                if (grow >= 0 && grow < LL)
                    v = *(const float4*)(inb + (size_t)grow * CC + c4 * 4);
                uint32_t h01 = pack_h2(v.x, v.y);
                uint32_t h23 = pack_h2(v.z, v.w);
                *(ull*)(sA2 + row * A_STR + c4 * 2) = ((ull)h23 << 32) | h01;
            }
        }
        stageB(0);                                  // g0
        if (tid < 64)
            CP_ASYNC16(sidx_u32 + tid * 16, g_idx + b * MEL + fbase + tid * 4);
        CP_COMMIT();                                // g1
        stageB(1);                                  // g2
        stageB(2);                                  // g3
    } else {
        stageB(0);                                  // g0
        // ---- A (packed h1) + idx slice, one commit group ----
        const uint32_t* apk = g_h1pk + (size_t)b * LL * 128;
#pragma unroll
        for (int i = 0; i < 9; i++) {
            int idx = tid + i * 256;               // need 66*32 = 2112 segs
            if (idx < 66 * 32) {
                int row = idx >> 5, seg = idx & 31;
                int grow = l0 + row - 1;
                if (grow >= 0 && grow < LL)
                    CP_ASYNC16(sa_u32 + (uint32_t)(row * A_STR + seg * 4) * 4,
                               apk + (size_t)grow * 128 + seg * 4);
                else
                    *(float4*)(sA2 + row * A_STR + seg * 4) =
                        make_float4(0.f, 0.f, 0.f, 0.f);
            }
        }
        if (tid < 64)
            CP_ASYNC16(sidx_u32 + tid * 16, g_idx + b * MEL + fbase + tid * 4);
        CP_COMMIT();                                // g1
        stageB(1);                                  // g2
        stageB(2);                                  // g3
    }

    float acc[4][4][4];
#pragma unroll
    for (int mt = 0; mt < 4; mt++)
#pragma unroll
        for (int nt = 0; nt < 4; nt++)
#pragma unroll
            for (int r = 0; r < 4; r++) acc[mt][nt][r] = 0.f;

    for (int it = 0; it < 12; it++) {
        const int ktap = it >> 2, koff = (it & 3) * 32;
        if (it <= 9) CP_WAIT2();
        else if (it == 10) CP_WAIT1();
        else CP_WAIT0();
        __syncthreads();
        if (it + 3 < 12) stageB(it + 3);

        // ---- regulate: issue gathers now; latency hides under MMA ----
        int ix[6];
        float4 vv[6];
#pragma unroll
        for (int u = 0; u < 6; u++) {
            int s = it * 6 + u;
            ix[u] = (s < 64) ? sIdx[(tid + s * 256) >> 6] : -1;
        }
#pragma unroll
        for (int u = 0; u < 6; u++) {
            vv[u] = make_float4(0.f, 0.f, 0.f, 0.f);
            if (ix[u] >= 0) {
                int s = it * 6 + u;
                int c4 = (tid + s * 256) & 63;
                vv[u] = *(const float4*)(xin + ((size_t)b * LL + ix[u]) * CC + c4 * 4);
            }
        }

        const uint32_t* ab = sA2 + (ktap + g) * A_STR + koff + q;
        const uint32_t* bb = (uint32_t*)(smu + A_U32 + (it & 3) * B32_U32) + n0 + g;
#pragma unroll
        for (int ks = 0; ks < 4; ks++) {
            uint32_t af[4][4], bf[4][2];
#pragma unroll
            for (int mt = 0; mt < 4; mt++) {
                const uint32_t* ap = ab + mt * (16 * A_STR) + ks * 8;
                af[mt][0] = ap[0];
                af[mt][1] = ap[8 * A_STR];
                af[mt][2] = ap[4];
                af[mt][3] = ap[8 * A_STR + 4];
            }
#pragma unroll
            for (int nt = 0; nt < 4; nt++) {
                bf[nt][0] = bb[(ks * 8 + q) * B_STR + nt * 8];
                bf[nt][1] = bb[(ks * 8 + q + 4) * B_STR + nt * 8];
            }
#pragma unroll
            for (int mt = 0; mt < 4; mt++)
#pragma unroll
                for (int nt = 0; nt < 4; nt++)
                    mma_f16(acc[mt][nt], af[mt], bf[nt]);
        }

        // ---- regulate stores ----
#pragma unroll
        for (int u = 0; u < 6; u++) {
            int s = it * 6 + u;
            if (s < 64) {
                int j = tid + s * 256;
                int fr = j >> 6, c4 = j & 63;
                *(float4*)(regout + ((size_t)b * MEL + fbase + fr) * CC + c4 * 4) = vv[u];
            }
        }
    }
    __syncthreads();

    // ---- epilogue: bias + ReLU + LN (fused), optional linear head ----
    float bi[8], ga[8], be[8], lw[8];
#pragma unroll
    for (int nt = 0; nt < 4; nt++)
#pragma unroll
        for (int j = 0; j < 2; j++) {
            int c = n0 + nt * 8 + 2 * q + j;
            bi[nt * 2 + j] = __ldg(bias + c);
            ga[nt * 2 + j] = __ldg(gamma + c);
            be[nt * 2 + j] = __ldg(beta + c);
            if (FINAL) lw[nt * 2 + j] = __ldg(linw + c);
        }

    float v[4][2][8];
    float2* red   = (float2*)sA2;                  // [64 rows][8 warps]
    float2* stats = red + 512;                     // [64]
    float*  dred  = (float*)sA2 + 2048;            // [64 rows][8 warps]

#pragma unroll
    for (int mt = 0; mt < 4; mt++)
#pragma unroll
        for (int h = 0; h < 2; h++) {
            float s = 0.f, s2 = 0.f;
#pragma unroll
            for (int nt = 0; nt < 4; nt++)
#pragma unroll
                for (int j = 0; j < 2; j++) {
                    float x = acc[mt][nt][h * 2 + j] + bi[nt * 2 + j];
                    x = fmaxf(x, 0.f);
                    v[mt][h][nt * 2 + j] = x;
                    s += x; s2 += x * x;
                }
            s  += __shfl_xor_sync(0xffffffffu, s, 1);
            s2 += __shfl_xor_sync(0xffffffffu, s2, 1);
            s  += __shfl_xor_sync(0xffffffffu, s, 2);
            s2 += __shfl_xor_sync(0xffffffffu, s2, 2);
            if (q == 0)
                red[(mt * 16 + g + 8 * h) * 8 + warp] = make_float2(s, s2);
        }
    __syncthreads();
    if (tid < 64) {
        float s = 0.f, s2 = 0.f;
#pragma unroll
        for (int wv = 0; wv < 8; wv++) {
            float2 p = red[tid * 8 + wv];
            s += p.x; s2 += p.y;
        }
        float mu = s * (1.f / 256.f);
        float var = s2 * (1.f / 256.f) - mu * mu;
        stats[tid] = make_float2(mu, rsqrtf(var + 1e-5f));
    }
    __syncthreads();

    if (!FINAL) {
#pragma unroll
        for (int mt = 0; mt < 4; mt++)
#pragma unroll
            for (int h = 0; h < 2; h++) {
                int r = mt * 16 + g + 8 * h;
                float2 st = stats[r];
                uint32_t* orow = g_h1pk + ((size_t)b * LL + l0 + r) * 128 + warp * 16;
#pragma unroll
                for (int nt = 0; nt < 4; nt++) {
                    float ox = (v[mt][h][nt * 2]     - st.x) * st.y * ga[nt * 2]     + be[nt * 2];
                    float oy = (v[mt][h][nt * 2 + 1] - st.x) * st.y * ga[nt * 2 + 1] + be[nt * 2 + 1];
                    orow[nt * 4 + q] = pack_h2(ox, oy);
                }
            }
    } else {
#pragma unroll
        for (int mt = 0; mt < 4; mt++)
#pragma unroll
            for (int h = 0; h < 2; h++) {
                int r = mt * 16 + g + 8 * h;
                float2 st = stats[r];
                float d = 0.f;
#pragma unroll
                for (int p = 0; p < 8; p++)
                    d += ((v[mt][h][p] - st.x) * st.y * ga[p] + be[p]) * lw[p];
                d += __shfl_xor_sync(0xffffffffu, d, 1);
                d += __shfl_xor_sync(0xffffffffu, d, 2);
                if (q == 0) dred[r * 8 + warp] = d;
            }
        __syncthreads();
        if (tid < 64) {
            float d = 0.f;
#pragma unroll
            for (int wv = 0; wv < 8; wv++) d += dred[tid * 8 + wv];
            predout[b * LL + l0 + tid] = d + __ldg(linb);
        }
    }
}

// ---------------------------------------------------------------------------
extern "C" void kernel_launch(void* const* d_in, const int* in_sizes, int n_in,
                              void* d_out, int out_size)
{
    const float* x    = (const float*)d_in[0];
    const int*   dur  = (const int*)d_in[1];
    const float* c1w  = (const float*)d_in[2];
    const float* c1b  = (const float*)d_in[3];
    const float* ln1g = (const float*)d_in[4];
    const float* ln1b = (const float*)d_in[5];
    const float* c2w  = (const float*)d_in[6];
    const float* c2b  = (const float*)d_in[7];
    const float* ln2g = (const float*)d_in[8];
    const float* ln2b = (const float*)d_in[9];
    const float* linw = (const float*)d_in[10];
    const float* linb = (const float*)d_in[11];

    float* out  = (float*)d_out;
    float* pred = out + (size_t)BB * MEL * CC;

    cudaFuncSetAttribute(conv_mma_kernel<false>,
                         cudaFuncAttributeMaxDynamicSharedMemorySize, SMEM_BYTES);
    cudaFuncSetAttribute(conv_mma_kernel<true>,
                         cudaFuncAttributeMaxDynamicSharedMemorySize, SMEM_BYTES);

    prep_kernel<<<48 + BB, 512>>>(c1w, c2w, dur);

    dim3 cgrid(LL / 64, BB);
    conv_mma_kernel<false><<<cgrid, 256, SMEM_BYTES>>>(x, c1b, ln1g, ln1b,
                                                       nullptr, nullptr, nullptr, out);
    conv_mma_kernel<true><<<cgrid, 256, SMEM_BYTES>>>(x, c2b, ln2g, ln2b,
                                                      linw, linb, pred, out);
}

// round 15
// speedup vs baseline: 1.0043x; 1.0005x over previous
#include <cuda_runtime.h>
#include <cuda_fp16.h>
#include <cstdint>

#define BB   16
#define LL   512
#define CC   256
#define MEL  4096

typedef unsigned long long ull;

// ---------------------------------------------------------------------------
// Scratch + flags (__device__ globals; flags consumer-reset => replay-safe)
// ---------------------------------------------------------------------------
__device__ uint32_t g_h1pk[BB * LL * 128];        // h1 packed half2 [b][l][kpair]
__device__ int      g_idx[BB * MEL];              // per-frame token index
__device__ uint32_t g_wpk[2 * 3 * 128 * 256];     // weights packed half2
__device__ int      g_fprep[128];                 // prep-done, one per conv1 CTA
__device__ unsigned g_prep_ct;                    // prep completion counter

#define P_CTAS 32

// ---------------------------------------------------------------------------
__device__ __forceinline__ uint32_t pack_h2(float a, float b) {
    __half2 h = __floats2half2_rn(a, b);
    return *reinterpret_cast<uint32_t*>(&h);
}
__device__ __forceinline__ void mma_f16(float* d, const uint32_t* a, const uint32_t* b) {
    asm volatile(
        "mma.sync.aligned.m16n8k16.row.col.f32.f16.f16.f32 "
        "{%0,%1,%2,%3}, {%4,%5,%6,%7}, {%8,%9}, {%0,%1,%2,%3};"
        : "+f"(d[0]), "+f"(d[1]), "+f"(d[2]), "+f"(d[3])
        : "r"(a[0]), "r"(a[1]), "r"(a[2]), "r"(a[3]), "r"(b[0]), "r"(b[1]));
}
__device__ __forceinline__ uint32_t smem_u32(const void* p) {
    uint32_t a;
    asm("{ .reg .u64 t; cvta.to.shared.u64 t, %1; cvt.u32.u64 %0, t; }"
        : "=r"(a) : "l"(p));
    return a;
}
__device__ __forceinline__ void spin_flag(int* p) {
    while (atomicAdd(p, 0) == 0) { __nanosleep(60); }
}
#define CP_ASYNC16(dst, src) \
    asm volatile("cp.async.ca.shared.global [%0], [%1], 16;" :: "r"(dst), "l"(src))
#define CP_COMMIT() asm volatile("cp.async.commit_group;" ::: "memory")
#define CP_WAIT2()  asm volatile("cp.async.wait_group 2;" ::: "memory")
#define CP_WAIT1()  asm volatile("cp.async.wait_group 1;" ::: "memory")
#define CP_WAIT0()  asm volatile("cp.async.wait_group 0;" ::: "memory")

// smem geometry (uint32 units).
#define A_STR 132
#define B_STR 264
#define A_U32 (66 * A_STR)               // 8712
#define B32_U32 (32 * B_STR)             // 8448 (one 32-kpair chunk)
#define IDX_OFF (A_U32 + 4 * B32_U32)    // 42504
#define SMEM_BYTES ((IDX_OFF + 256) * 4) // 171040

// ---------------------------------------------------------------------------
// Conv body: conv1d(K=3,SAME)+bias+ReLU+LN [+linear head if FINAL], fp16 MMA.
// CTA = [64 l x 256 f], 256 threads / 8 warps, warp tile 64x32.
// FINAL=false: A packed inline from fp32 x (overlaps prep), spin on prep flag.
// FINAL=true : A via cp.async from packed h1 (stream order guarantees ready).
// ---------------------------------------------------------------------------
template <bool FINAL>
__device__ __forceinline__ void conv_body(
    int b, int t, int c1id,
    const float* __restrict__ xin,
    const float* __restrict__ bias,
    const float* __restrict__ gamma,
    const float* __restrict__ beta,
    const float* __restrict__ linw,
    const float* __restrict__ linb,
    float* __restrict__ predout,
    float* __restrict__ regout,
    uint32_t* smu)
{
    uint32_t* sA2 = smu;
    int* sIdx = (int*)(smu + IDX_OFF);
    const uint32_t sa_u32 = smem_u32(sA2);
    const uint32_t sb_base = sa_u32 + A_U32 * 4;
    const uint32_t sidx_u32 = smem_u32(sIdx);

    const int tid  = threadIdx.x;
    const int warp = tid >> 5, lane = tid & 31;
    const int g = lane >> 2, q = lane & 3;
    const int n0 = warp * 32;
    const int l0 = t * 64;
    const int CONV = FINAL ? 1 : 0;
    const int fbase = t * 512 + (FINAL ? 256 : 0);

    auto stageB = [&](int ck) {
        const int buf = ck & 3;
        const uint32_t* src = g_wpk + ((size_t)(CONV * 3 + (ck >> 2)) * 128 + (ck & 3) * 32) * 256;
        const uint32_t bdst = sb_base + (uint32_t)buf * B32_U32 * 4;
#pragma unroll
        for (int i = 0; i < 8; i++) {
            int idx = tid + i * 256;
            int c = idx >> 6, n4 = idx & 63;
            CP_ASYNC16(bdst + (uint32_t)(c * B_STR + n4 * 4) * 4,
                       src + (size_t)c * 256 + n4 * 4);
        }
        CP_COMMIT();
    };

    if (!FINAL) {
        // ---- A inline pack from fp32 x (overlaps prep on other SMs) ----
        const float* inb = xin + (size_t)b * LL * CC;
#pragma unroll 4
        for (int i = 0; i < 17; i++) {
            int idx = tid + i * 256;               // need 66*64 = 4224
            if (idx < 66 * 64) {
                int c4 = idx & 63, row = idx >> 6;
                int grow = l0 + row - 1;
                float4 v = make_float4(0.f, 0.f, 0.f, 0.f);
                if (grow >= 0 && grow < LL)
                    v = *(const float4*)(inb + (size_t)grow * CC + c4 * 4);
                uint32_t h01 = pack_h2(v.x, v.y);
                uint32_t h23 = pack_h2(v.z, v.w);
                *(ull*)(sA2 + row * A_STR + c4 * 2) = ((ull)h23 << 32) | h01;
            }
        }
        // ---- wait for prep (weights + idx) ----
        if (tid == 0) {
            spin_flag(&g_fprep[c1id]);
            g_fprep[c1id] = 0;
            __threadfence();
        }
        __syncthreads();
        stageB(0);                                  // g0
        if (tid < 64)
            CP_ASYNC16(sidx_u32 + tid * 16, g_idx + b * MEL + fbase + tid * 4);
        CP_COMMIT();                                // g1
        stageB(1);                                  // g2
        stageB(2);                                  // g3
    } else {
        stageB(0);                                  // g0
        // ---- A (packed h1) + idx slice, one commit group ----
        const uint32_t* apk = g_h1pk + (size_t)b * LL * 128;
#pragma unroll
        for (int i = 0; i < 9; i++) {
            int idx = tid + i * 256;               // need 66*32 = 2112 segs
            if (idx < 66 * 32) {
                int row = idx >> 5, seg = idx & 31;
                int grow = l0 + row - 1;
                if (grow >= 0 && grow < LL)
                    CP_ASYNC16(sa_u32 + (uint32_t)(row * A_STR + seg * 4) * 4,
                               apk + (size_t)grow * 128 + seg * 4);
                else
                    *(float4*)(sA2 + row * A_STR + seg * 4) =
                        make_float4(0.f, 0.f, 0.f, 0.f);
            }
        }
        if (tid < 64)
            CP_ASYNC16(sidx_u32 + tid * 16, g_idx + b * MEL + fbase + tid * 4);
        CP_COMMIT();                                // g1
        stageB(1);                                  // g2
        stageB(2);                                  // g3
    }

    float acc[4][4][4];
#pragma unroll
    for (int mt = 0; mt < 4; mt++)
#pragma unroll
        for (int nt = 0; nt < 4; nt++)
#pragma unroll
            for (int r = 0; r < 4; r++) acc[mt][nt][r] = 0.f;

    for (int it = 0; it < 12; it++) {
        const int ktap = it >> 2, koff = (it & 3) * 32;
        if (it <= 9) CP_WAIT2();
        else if (it == 10) CP_WAIT1();
        else CP_WAIT0();
        __syncthreads();
        if (it + 3 < 12) stageB(it + 3);

        // ---- regulate: issue gathers now; latency hides under MMA ----
        int ix[6];
        float4 vv[6];
#pragma unroll
        for (int u = 0; u < 6; u++) {
            int s = it * 6 + u;
            ix[u] = (s < 64) ? sIdx[(tid + s * 256) >> 6] : -1;
        }
#pragma unroll
        for (int u = 0; u < 6; u++) {
            vv[u] = make_float4(0.f, 0.f, 0.f, 0.f);
            if (ix[u] >= 0) {
                int s = it * 6 + u;
                int c4 = (tid + s * 256) & 63;
                vv[u] = *(const float4*)(xin + ((size_t)b * LL + ix[u]) * CC + c4 * 4);
            }
        }

        const uint32_t* ab = sA2 + (ktap + g) * A_STR + koff + q;
        const uint32_t* bb = (uint32_t*)(smu + A_U32 + (it & 3) * B32_U32) + n0 + g;
#pragma unroll
        for (int ks = 0; ks < 4; ks++) {
            uint32_t af[4][4], bf[4][2];
#pragma unroll
            for (int mt = 0; mt < 4; mt++) {
                const uint32_t* ap = ab + mt * (16 * A_STR) + ks * 8;
                af[mt][0] = ap[0];
                af[mt][1] = ap[8 * A_STR];
                af[mt][2] = ap[4];
                af[mt][3] = ap[8 * A_STR + 4];
            }
#pragma unroll
            for (int nt = 0; nt < 4; nt++) {
                bf[nt][0] = bb[(ks * 8 + q) * B_STR + nt * 8];
                bf[nt][1] = bb[(ks * 8 + q + 4) * B_STR + nt * 8];
            }
#pragma unroll
            for (int mt = 0; mt < 4; mt++)
#pragma unroll
                for (int nt = 0; nt < 4; nt++)
                    mma_f16(acc[mt][nt], af[mt], bf[nt]);
        }

        // ---- regulate stores ----
#pragma unroll
        for (int u = 0; u < 6; u++) {
            int s = it * 6 + u;
            if (s < 64) {
                int j = tid + s * 256;
                int fr = j >> 6, c4 = j & 63;
                *(float4*)(regout + ((size_t)b * MEL + fbase + fr) * CC + c4 * 4) = vv[u];
            }
        }
    }
    __syncthreads();

    // ---- epilogue: bias + ReLU + LN (fused), optional linear head ----
    float bi[8], ga[8], be[8], lw[8];
#pragma unroll
    for (int nt = 0; nt < 4; nt++)
#pragma unroll
        for (int j = 0; j < 2; j++) {
            int c = n0 + nt * 8 + 2 * q + j;
            bi[nt * 2 + j] = __ldg(bias + c);
            ga[nt * 2 + j] = __ldg(gamma + c);
            be[nt * 2 + j] = __ldg(beta + c);
            if (FINAL) lw[nt * 2 + j] = __ldg(linw + c);
        }

    float v[4][2][8];
    float2* red   = (float2*)sA2;                  // [64 rows][8 warps]
    float2* stats = red + 512;                     // [64]
    float*  dred  = (float*)sA2 + 2048;            // [64 rows][8 warps]

#pragma unroll
    for (int mt = 0; mt < 4; mt++)
#pragma unroll
        for (int h = 0; h < 2; h++) {
            float s = 0.f, s2 = 0.f;
#pragma unroll
            for (int nt = 0; nt < 4; nt++)
#pragma unroll
                for (int j = 0; j < 2; j++) {
                    float x = acc[mt][nt][h * 2 + j] + bi[nt * 2 + j];
                    x = fmaxf(x, 0.f);
                    v[mt][h][nt * 2 + j] = x;
                    s += x; s2 += x * x;
                }
            s  += __shfl_xor_sync(0xffffffffu, s, 1);
            s2 += __shfl_xor_sync(0xffffffffu, s2, 1);
            s  += __shfl_xor_sync(0xffffffffu, s, 2);
            s2 += __shfl_xor_sync(0xffffffffu, s2, 2);
            if (q == 0)
                red[(mt * 16 + g + 8 * h) * 8 + warp] = make_float2(s, s2);
        }
    __syncthreads();
    if (tid < 64) {
        float s = 0.f, s2 = 0.f;
#pragma unroll
        for (int wv = 0; wv < 8; wv++) {
            float2 p = red[tid * 8 + wv];
            s += p.x; s2 += p.y;
        }
        float mu = s * (1.f / 256.f);
        float var = s2 * (1.f / 256.f) - mu * mu;
        stats[tid] = make_float2(mu, rsqrtf(var + 1e-5f));
    }
    __syncthreads();

    if (!FINAL) {
#pragma unroll
        for (int mt = 0; mt < 4; mt++)
#pragma unroll
            for (int h = 0; h < 2; h++) {
                int r = mt * 16 + g + 8 * h;
                float2 st = stats[r];
                uint32_t* orow = g_h1pk + ((size_t)b * LL + l0 + r) * 128 + warp * 16;
#pragma unroll
                for (int nt = 0; nt < 4; nt++) {
                    float ox = (v[mt][h][nt * 2]     - st.x) * st.y * ga[nt * 2]     + be[nt * 2];
                    float oy = (v[mt][h][nt * 2 + 1] - st.x) * st.y * ga[nt * 2 + 1] + be[nt * 2 + 1];
                    orow[nt * 4 + q] = pack_h2(ox, oy);
                }
            }
    } else {
#pragma unroll
        for (int mt = 0; mt < 4; mt++)
#pragma unroll
            for (int h = 0; h < 2; h++) {
                int r = mt * 16 + g + 8 * h;
                float2 st = stats[r];
                float d = 0.f;
#pragma unroll
                for (int p = 0; p < 8; p++)
                    d += ((v[mt][h][p] - st.x) * st.y * ga[p] + be[p]) * lw[p];
                d += __shfl_xor_sync(0xffffffffu, d, 1);
                d += __shfl_xor_sync(0xffffffffu, d, 2);
                if (q == 0) dred[r * 8 + warp] = d;
            }
        __syncthreads();
        if (tid < 64) {
            float d = 0.f;
#pragma unroll
            for (int wv = 0; wv < 8; wv++) d += dred[tid * 8 + wv];
            predout[b * LL + l0 + tid] = d + __ldg(linb);
        }
    }
}

// ---------------------------------------------------------------------------
// Launch 1: bids 0..15 w-pack, 16..31 cumsum/idx, 32..159 conv1
// ---------------------------------------------------------------------------
__global__ void __launch_bounds__(256, 1)
prep_conv1_kernel(const float* __restrict__ x,
                  const int*   __restrict__ dur,
                  const float* __restrict__ w1,
                  const float* __restrict__ w2,
                  const float* __restrict__ c1b,
                  const float* __restrict__ ln1g,
                  const float* __restrict__ ln1b,
                  float* __restrict__ outp)
{
    extern __shared__ __align__(16) uint32_t smu[];
    const int bid = blockIdx.x;
    const int tid = threadIdx.x;

    if (bid < P_CTAS) {
        if (bid < 16) {
            // ---- weight fp16 pack: 16 blocks x 256 thr x 12 items = 49152 ----
            int base = bid * 256 + tid;
#pragma unroll
            for (int r = 0; r < 12; r++) {
                int id = base + r * 4096;
                int n4 = id & 63;
                int kp = (id >> 6) & 127;
                int tt = id >> 13;                 // 0..5
                int tap = tt % 3, conv = tt / 3;
                const float* src = (conv ? w2 : w1) + (size_t)tap * 65536
                                 + (size_t)(2 * kp) * 256 + n4 * 4;
                float4 lo = *(const float4*)(src);
                float4 hi = *(const float4*)(src + 256);
                uint4 o;
                o.x = pack_h2(lo.x, hi.x);
                o.y = pack_h2(lo.y, hi.y);
                o.z = pack_h2(lo.z, hi.z);
                o.w = pack_h2(lo.w, hi.w);
                *(uint4*)(g_wpk + ((size_t)(conv * 3 + tap) * 128 + kp) * 256 + n4 * 4) = o;
            }
        } else {
            // ---- cumsum + frame->token idx (b = bid-16), 256 threads ----
            int* s = (int*)smu;
            int* wsum = s + 512;
            int b = bid - 16;
            int lane = tid & 31, wid = tid >> 5;
            int d0 = dur[b * LL + 2 * tid];
            int d1 = dur[b * LL + 2 * tid + 1];
            int v = d0 + d1;
#pragma unroll
            for (int off = 1; off < 32; off <<= 1) {
                int tmp = __shfl_up_sync(0xffffffffu, v, off);
                if (lane >= off) v += tmp;
            }
            if (lane == 31) wsum[wid] = v;
            __syncthreads();
            if (wid == 0 && lane < 8) {
                int w = wsum[lane];
#pragma unroll
                for (int off = 1; off < 8; off <<= 1) {
                    int tmp = __shfl_up_sync(0xffu, w, off);
                    if (lane >= off) w += tmp;
                }
                wsum[lane] = w;
            }
            __syncthreads();
            int incl = v + (wid > 0 ? wsum[wid - 1] : 0);
            s[2 * tid]     = incl - d1;
            s[2 * tid + 1] = incl;
            __syncthreads();
            int total = s[LL - 1];
#pragma unroll
            for (int r = 0; r < 16; r++) {
                int tt = tid + r * 256;
                int lo = 0, hi = LL;
                while (lo < hi) {
                    int mid = (lo + hi) >> 1;
                    if (s[mid] <= tt) lo = mid + 1; else hi = mid;
                }
                g_idx[b * MEL + tt] = (tt < total) ? min(lo, LL - 1) : -1;
            }
        }
        // ---- prep completion: last CTA releases all conv1 CTAs ----
        __threadfence();
        __syncthreads();
        if (tid == 0) {
            unsigned c = atomicAdd(&g_prep_ct, 1u);
            if ((c % (unsigned)P_CTAS) == (unsigned)(P_CTAS - 1)) {
                for (int i = 0; i < 128; i++) atomicExch(&g_fprep[i], 1);
            }
        }
        return;
    }

    int id = bid - P_CTAS;
    conv_body<false>(id >> 3, id & 7, id, x, c1b, ln1g, ln1b,
                     nullptr, nullptr, nullptr, outp, smu);
}

// ---------------------------------------------------------------------------
// Launch 2: conv2 (stream-ordered after launch 1; no spinning)
// ---------------------------------------------------------------------------
__global__ void __launch_bounds__(256, 1)
conv2_kernel(const float* __restrict__ x,
             const float* __restrict__ c2b,
             const float* __restrict__ ln2g,
             const float* __restrict__ ln2b,
             const float* __restrict__ linw,
             const float* __restrict__ linb,
             float* __restrict__ pred,
             float* __restrict__ outp)
{
    extern __shared__ __align__(16) uint32_t smu[];
    conv_body<true>(blockIdx.y, blockIdx.x, 0, x, c2b, ln2g, ln2b,
                    linw, linb, pred, outp, smu);
}

// ---------------------------------------------------------------------------
extern "C" void kernel_launch(void* const* d_in, const int* in_sizes, int n_in,
                              void* d_out, int out_size)
{
    const float* x    = (const float*)d_in[0];
    const int*   dur  = (const int*)d_in[1];
    const float* c1w  = (const float*)d_in[2];
    const float* c1b  = (const float*)d_in[3];
    const float* ln1g = (const float*)d_in[4];
    const float* ln1b = (const float*)d_in[5];
    const float* c2w  = (const float*)d_in[6];
    const float* c2b  = (const float*)d_in[7];
    const float* ln2g = (const float*)d_in[8];
    const float* ln2b = (const float*)d_in[9];
    const float* linw = (const float*)d_in[10];
    const float* linb = (const float*)d_in[11];

    float* out  = (float*)d_out;
    float* pred = out + (size_t)BB * MEL * CC;

    cudaFuncSetAttribute(prep_conv1_kernel,
                         cudaFuncAttributeMaxDynamicSharedMemorySize, SMEM_BYTES);
    cudaFuncSetAttribute(conv2_kernel,
                         cudaFuncAttributeMaxDynamicSharedMemorySize, SMEM_BYTES);

    prep_conv1_kernel<<<P_CTAS + 128, 256, SMEM_BYTES>>>(x, dur, c1w, c2w,
                                                         c1b, ln1g, ln1b, out);

    dim3 cgrid(LL / 64, BB);
    conv2_kernel<<<cgrid, 256, SMEM_BYTES>>>(x, c2b, ln2g, ln2b,
                                             linw, linb, pred, out);
}